// round 9
// baseline (speedup 1.0000x reference)
#include <cuda_runtime.h>
#include <cuda_bf16.h>
#include <cstdint>

#define E_DIM 1024
#define T_DIM 8192

// Scratch: QKV for the 16384 dilated tokens, layout [row][384] = Q|K|V.
__device__ float g_qkv[16384 * 384];
// Pre-split gathered X, bf16 hi/lo planes [16384][1024]
__device__ __nv_bfloat16 g_xhi[16384 * 1024];
__device__ __nv_bfloat16 g_xlo[16384 * 1024];
// Pre-split weights, rows 0-127=Wq, 128-255=Wk, 256-383=Wv
__device__ __nv_bfloat16 g_whi[384 * 1024];
__device__ __nv_bfloat16 g_wlo[384 * 1024];
// Gathered positional bias p_bias[k][o]
__device__ float g_pbias[64 * 64];
// Per-m-block completion counters (3 slabs each)
__device__ int g_ready[128];

__device__ __forceinline__ uint32_t smem_u32(const void* p) {
    uint32_t a;
    asm("{ .reg .u64 t; cvta.to.shared.u64 t, %1; cvt.u32.u64 %0, t; }" : "=r"(a) : "l"(p));
    return a;
}

#define LDSM4(r, addr) \
    asm volatile("ldmatrix.sync.aligned.m8n8.x4.shared.b16 {%0,%1,%2,%3}, [%4];" \
        : "=r"((r)[0]), "=r"((r)[1]), "=r"((r)[2]), "=r"((r)[3]) : "r"(addr))

#define MMA16816(c, a, b0, b1) \
    asm volatile("mma.sync.aligned.m16n8k16.row.col.f32.bf16.bf16.f32 " \
        "{%0,%1,%2,%3}, {%4,%5,%6,%7}, {%8,%9}, {%0,%1,%2,%3};" \
        : "+f"((c)[0]), "+f"((c)[1]), "+f"((c)[2]), "+f"((c)[3]) \
        : "r"((a)[0]), "r"((a)[1]), "r"((a)[2]), "r"((a)[3]), "r"(b0), "r"(b1))

__device__ __forceinline__ void cp16(uint32_t dst, const void* src) {
    asm volatile("cp.async.cg.shared.global [%0], [%1], 16;" :: "r"(dst), "l"(src));
}
#define CP_COMMIT() asm volatile("cp.async.commit_group;" ::: "memory")

// prep: split gathered X rows and W rows to bf16 hi/lo; gather p_bias; reset flags.
// blocks 0..16383: one X row; 16384..16767: one W row; 16768: pbias + flags.
__global__ __launch_bounds__(256) void prep_kernel(
    const float* __restrict__ x,
    const float* __restrict__ Wq, const float* __restrict__ Wk,
    const float* __restrict__ Wv, const float* __restrict__ P)
{
    const int blk = blockIdx.x;
    const int t = threadIdx.x;
    if (blk < 16768) {
        const float4* src;
        __nv_bfloat16 *dh, *dl;
        if (blk < 16384) {
            int b = blk >> 12, j = (blk >> 6) & 63, l = blk & 63;
            src = reinterpret_cast<const float4*>(
                x + ((size_t)b * T_DIM + (size_t)l * 128 + j) * E_DIM);
            dh = g_xhi + (size_t)blk * 1024;
            dl = g_xlo + (size_t)blk * 1024;
        } else {
            int r = blk - 16384;
            const float* W = (r < 128) ? Wq : (r < 256) ? Wk : Wv;
            src = reinterpret_cast<const float4*>(W + (size_t)(r & 127) * 1024);
            dh = g_whi + (size_t)r * 1024;
            dl = g_wlo + (size_t)r * 1024;
        }
        float4 v = src[t];
        __nv_bfloat162 h0 = __floats2bfloat162_rn(v.x, v.y);
        __nv_bfloat162 h1 = __floats2bfloat162_rn(v.z, v.w);
        __nv_bfloat162 l0 = __floats2bfloat162_rn(v.x - __bfloat162float(h0.x),
                                                  v.y - __bfloat162float(h0.y));
        __nv_bfloat162 l1 = __floats2bfloat162_rn(v.z - __bfloat162float(h1.x),
                                                  v.w - __bfloat162float(h1.y));
        uint2 hw = make_uint2(*reinterpret_cast<uint32_t*>(&h0), *reinterpret_cast<uint32_t*>(&h1));
        uint2 lw = make_uint2(*reinterpret_cast<uint32_t*>(&l0), *reinterpret_cast<uint32_t*>(&l1));
        *reinterpret_cast<uint2*>(dh + t * 4) = hw;
        *reinterpret_cast<uint2*>(dl + t * 4) = lw;
    } else {
        if (t < 128) g_ready[t] = 0;
        #pragma unroll
        for (int it = 0; it < 16; it++) {
            int i = t + it * 256;
            g_pbias[i] = P[(size_t)(i >> 6) * 128 * T_DIM + (size_t)(i & 63) * 128];
        }
    }
}

// ---- fused GEMM+attention ----
// bids 0..383:  GEMM slab = bid%3, m-block = bid/3
// bids 384..639: attention group g = bid-384, waits g_ready[g>>1] == 3
// GEMM stage (40960B): Ahi[128x80]@0, Alo@10240, Bhi@20480, Blo@30720. 2 stages.
#define STG 40960

__global__ __launch_bounds__(256, 2) void fused_kernel(float* __restrict__ out)
{
    extern __shared__ char dsm[];
    const int bid = blockIdx.x;
    const int tid = threadIdx.x;

    if (bid < 384) {
        // ================= GEMM: pure ldsm + MMA inner loop =================
        const uint32_t smem_base = smem_u32(dsm);
        const int warp = tid >> 5, lane = tid & 31;
        const int nbase = (bid % 3) * 128;
        const int m0 = (bid / 3) * 128;

        // loader: 2 threads/row, 32B each; rows 0..127 for both A and B
        const int lrow = tid >> 1;
        const int half = (tid & 1) * 32;
        const char* pAh = (const char*)g_xhi + (size_t)(m0 + lrow) * 2048 + half;
        const char* pAl = (const char*)g_xlo + (size_t)(m0 + lrow) * 2048 + half;
        const char* pBh = (const char*)g_whi + (size_t)(nbase + lrow) * 2048 + half;
        const char* pBl = (const char*)g_wlo + (size_t)(nbase + lrow) * 2048 + half;
        const uint32_t dst0 = lrow * 80 + half;

        auto issue_stage = [&](int slot, int k2) {
            uint32_t sb = smem_base + slot * STG + dst0;
            cp16(sb, pAh + k2);            cp16(sb + 16, pAh + k2 + 16);
            cp16(sb + 10240, pAl + k2);    cp16(sb + 10256, pAl + k2 + 16);
            cp16(sb + 20480, pBh + k2);    cp16(sb + 20496, pBh + k2 + 16);
            cp16(sb + 30720, pBl + k2);    cp16(sb + 30736, pBl + k2 + 16);
        };

        const int m_w = (warp >> 1) * 32;
        const int n_w = (warp & 1) * 64;

        float acc[2][8][4];
        #pragma unroll
        for (int i = 0; i < 2; i++)
            #pragma unroll
            for (int j = 0; j < 8; j++)
                #pragma unroll
                for (int k = 0; k < 4; k++) acc[i][j][k] = 0.f;

        issue_stage(0, 0);  CP_COMMIT();
        issue_stage(1, 64); CP_COMMIT();

        for (int c = 0; c < 32; c++) {
            asm volatile("cp.async.wait_group 1;" ::: "memory");
            __syncthreads();

            const uint32_t st = smem_base + (c & 1) * STG;

            #pragma unroll
            for (int kst = 0; kst < 2; kst++) {
                uint32_t ah[2][4], al[2][4];
                #pragma unroll
                for (int mt = 0; mt < 2; mt++) {
                    uint32_t ra = st + (m_w + mt * 16 + (lane & 15)) * 80
                                + kst * 32 + (lane >> 4) * 16;
                    LDSM4(ah[mt], ra);
                    LDSM4(al[mt], ra + 10240);
                }
                #pragma unroll
                for (int nh = 0; nh < 2; nh++) {
                    uint32_t bh[2][4], bl[2][4];
                    #pragma unroll
                    for (int q = 0; q < 2; q++) {
                        uint32_t rb = st + 20480 + (n_w + nh * 32 + q * 16 + (lane & 15)) * 80
                                    + kst * 32 + (lane >> 4) * 16;
                        LDSM4(bh[q], rb);
                        LDSM4(bl[q], rb + 10240);
                    }
                    #pragma unroll
                    for (int mt = 0; mt < 2; mt++)
                        #pragma unroll
                        for (int t = 0; t < 4; t++) {
                            const int q = t >> 1, s = t & 1;
                            MMA16816(acc[mt][nh * 4 + q * 2 + s], ah[mt], bh[q][s], bh[q][s + 2]);
                        }
                    #pragma unroll
                    for (int mt = 0; mt < 2; mt++)
                        #pragma unroll
                        for (int t = 0; t < 4; t++) {
                            const int q = t >> 1, s = t & 1;
                            MMA16816(acc[mt][nh * 4 + q * 2 + s], ah[mt], bl[q][s], bl[q][s + 2]);
                        }
                    #pragma unroll
                    for (int mt = 0; mt < 2; mt++)
                        #pragma unroll
                        for (int t = 0; t < 4; t++) {
                            const int q = t >> 1, s = t & 1;
                            MMA16816(acc[mt][nh * 4 + q * 2 + s], al[mt], bh[q][s], bh[q][s + 2]);
                        }
                }
            }

            __syncthreads();
            if (c < 30) issue_stage(c & 1, (c + 2) * 64);
            CP_COMMIT();
        }

        #pragma unroll
        for (int mt = 0; mt < 2; mt++) {
            #pragma unroll
            for (int nt = 0; nt < 8; nt++) {
                int row0 = m0 + m_w + mt * 16 + (lane >> 2);
                int col = nbase + n_w + nt * 8 + (lane & 3) * 2;
                float* p0 = &g_qkv[(size_t)row0 * 384 + col];
                float* p1 = &g_qkv[(size_t)(row0 + 8) * 384 + col];
                *reinterpret_cast<float2*>(p0) = make_float2(acc[mt][nt][0], acc[mt][nt][1]);
                *reinterpret_cast<float2*>(p1) = make_float2(acc[mt][nt][2], acc[mt][nt][3]);
            }
        }
        __threadfence();
        __syncthreads();
        if (tid == 0) atomicAdd(&g_ready[bid / 3], 1);

    } else {
        // ================= attention part =================
        float* sm = reinterpret_cast<float*>(dsm);
        float* Kt  = sm;                  // [128][68] transposed: Kt[p][k]
        float* Vs  = Kt + 128 * 68;       // [64][128]
        float* QtS = Vs + 64 * 128;       // [128][68] Qt[p][o], overlaid by S[64][68]
        const int g = bid - 384;
        const int mb = g >> 1;
        const int bbk = g >> 6, jseg = g & 63;
        const float* base = g_qkv + (size_t)g * 64 * 384;

        if (tid == 0) {
            int v;
            do {
                asm volatile("ld.acquire.gpu.s32 %0, [%1];" : "=r"(v) : "l"(g_ready + mb));
                if (v < 3) __nanosleep(128);
            } while (v < 3);
        }
        __syncthreads();

        for (int idx = tid; idx < 64 * 32; idx += 256) {
            int row = idx >> 5;
            int c4 = (idx & 31) * 4;
            const float* rp = base + (size_t)row * 384;
            float4 qv = *reinterpret_cast<const float4*>(rp + c4);
            float4 kv = *reinterpret_cast<const float4*>(rp + 128 + c4);
            float4 vv = *reinterpret_cast<const float4*>(rp + 256 + c4);
            *reinterpret_cast<float4*>(Vs + row * 128 + c4) = vv;
            Kt[(c4 + 0) * 68 + row] = kv.x;
            Kt[(c4 + 1) * 68 + row] = kv.y;
            Kt[(c4 + 2) * 68 + row] = kv.z;
            Kt[(c4 + 3) * 68 + row] = kv.w;
            QtS[(c4 + 0) * 68 + row] = qv.x;
            QtS[(c4 + 1) * 68 + row] = qv.y;
            QtS[(c4 + 2) * 68 + row] = qv.z;
            QtS[(c4 + 3) * 68 + row] = qv.w;
        }
        __syncthreads();

        const int tk = tid >> 4, to = tid & 15;
        float4 sval[4];
        {
            float sacc[4][4];
            #pragma unroll
            for (int i = 0; i < 4; i++)
                #pragma unroll
                for (int j = 0; j < 4; j++) sacc[i][j] = 0.f;
            for (int p = 0; p < 128; p++) {
                float4 rk = *reinterpret_cast<const float4*>(Kt + p * 68 + tk * 4);
                float4 rq = *reinterpret_cast<const float4*>(QtS + p * 68 + to * 4);
                float ka[4] = {rk.x, rk.y, rk.z, rk.w};
                float qa[4] = {rq.x, rq.y, rq.z, rq.w};
                #pragma unroll
                for (int i = 0; i < 4; i++)
                    #pragma unroll
                    for (int j = 0; j < 4; j++)
                        sacc[i][j] = fmaf(ka[i], qa[j], sacc[i][j]);
            }
            const float nf = 0.08838834764831845f;  // 1/sqrt(128)
            #pragma unroll
            for (int i = 0; i < 4; i++) {
                int k = tk * 4 + i;
                float e[4];
                #pragma unroll
                for (int j = 0; j < 4; j++) {
                    int o = to * 4 + j;
                    float v = (k >= o) ? sacc[i][j] : -10000.0f;
                    v += g_pbias[k * 64 + o];
                    e[j] = v * nf;
                }
                sval[i] = make_float4(e[0], e[1], e[2], e[3]);
            }
        }
        __syncthreads();
        #pragma unroll
        for (int i = 0; i < 4; i++)
            *reinterpret_cast<float4*>(QtS + (tk * 4 + i) * 68 + to * 4) = sval[i];
        __syncthreads();

        {
            const int o = tid >> 2, seg = tid & 3;
            float e[16];
            float mx = -3.402823466e38f;
            #pragma unroll
            for (int i = 0; i < 16; i++) {
                e[i] = QtS[(seg * 16 + i) * 68 + o];
                mx = fmaxf(mx, e[i]);
            }
            mx = fmaxf(mx, __shfl_xor_sync(0xffffffffu, mx, 1));
            mx = fmaxf(mx, __shfl_xor_sync(0xffffffffu, mx, 2));
            float ssum = 0.f;
            #pragma unroll
            for (int i = 0; i < 16; i++) { e[i] = __expf(e[i] - mx); ssum += e[i]; }
            ssum += __shfl_xor_sync(0xffffffffu, ssum, 1);
            ssum += __shfl_xor_sync(0xffffffffu, ssum, 2);
            float inv = 1.0f / ssum;
            #pragma unroll
            for (int i = 0; i < 16; i++)
                QtS[(seg * 16 + i) * 68 + o] = e[i] * inv;
        }
        __syncthreads();

        {
            const int td = tid >> 4, tmm = tid & 15;
            float acc[4][8];
            #pragma unroll
            for (int i = 0; i < 4; i++)
                #pragma unroll
                for (int j = 0; j < 8; j++) acc[i][j] = 0.f;
            for (int k = 0; k < 64; k++) {
                float4 rs4 = *reinterpret_cast<const float4*>(QtS + k * 68 + td * 4);
                float rs[4] = {rs4.x, rs4.y, rs4.z, rs4.w};
                float4 v0 = *reinterpret_cast<const float4*>(Vs + k * 128 + tmm * 8);
                float4 v1 = *reinterpret_cast<const float4*>(Vs + k * 128 + tmm * 8 + 4);
                float rv[8] = {v0.x, v0.y, v0.z, v0.w, v1.x, v1.y, v1.z, v1.w};
                #pragma unroll
                for (int i = 0; i < 4; i++)
                    #pragma unroll
                    for (int j = 0; j < 8; j++)
                        acc[i][j] = fmaf(rs[i], rv[j], acc[i][j]);
            }
            const float4 z = make_float4(0.f, 0.f, 0.f, 0.f);
            #pragma unroll
            for (int i = 0; i < 4; i++) {
                int d = td * 4 + i;
                size_t orow = (size_t)bbk * T_DIM + 2 * ((size_t)jseg * 64 + d);
                float* op = out + orow * 128 + tmm * 8;
                *reinterpret_cast<float4*>(op)     = make_float4(acc[i][0], acc[i][1], acc[i][2], acc[i][3]);
                *reinterpret_cast<float4*>(op + 4) = make_float4(acc[i][4], acc[i][5], acc[i][6], acc[i][7]);
                float* oz = op + 128;   // odd row (poisoned) -> zero
                *reinterpret_cast<float4*>(oz)     = z;
                *reinterpret_cast<float4*>(oz + 4) = z;
            }
        }
    }
}

extern "C" void kernel_launch(void* const* d_in, const int* in_sizes, int n_in,
                              void* d_out, int out_size) {
    const float* x  = (const float*)d_in[0];   // x_in  [4, 8192, 1024]
    const float* P  = (const float*)d_in[1];   // P     [8192, 8192]
    const float* Wk = (const float*)d_in[2];   // Wk    [128, 1024]
    const float* Wq = (const float*)d_in[3];   // Wq    [128, 1024]
    const float* Wv = (const float*)d_in[4];   // Wv    [128, 1024]
    float* out = (float*)d_out;                // [4, 8192, 128] fp32

    prep_kernel<<<16769, 256>>>(x, Wq, Wk, Wv, P);

    // attn smem need: (128*68 + 64*128 + 128*68)*4 = 102400 B (> GEMM's 81920)
    int fsm = 102400;
    cudaFuncSetAttribute(fused_kernel, cudaFuncAttributeMaxDynamicSharedMemorySize, fsm);
    fused_kernel<<<640, 256, fsm>>>(out);
}

// round 10
// speedup vs baseline: 1.1457x; 1.1457x over previous
#include <cuda_runtime.h>
#include <cuda_bf16.h>
#include <cstdint>

#define E_DIM 1024
#define T_DIM 8192

// Scratch: QKV for the 16384 dilated tokens, layout [row][384] = Q|K|V.
__device__ float g_qkv[16384 * 384];
// Pre-split weights, rows 0-127=Wq, 128-255=Wk, 256-383=Wv
__device__ __nv_bfloat16 g_whi[384 * 1024];
__device__ __nv_bfloat16 g_wlo[384 * 1024];
// Gathered positional bias p_bias[k][o]
__device__ float g_pbias[64 * 64];
// Per-m-block completion counters (3 slabs each)
__device__ int g_ready[128];

__device__ __forceinline__ uint32_t smem_u32(const void* p) {
    uint32_t a;
    asm("{ .reg .u64 t; cvta.to.shared.u64 t, %1; cvt.u32.u64 %0, t; }" : "=r"(a) : "l"(p));
    return a;
}

#define LDSM4(r, addr) \
    asm volatile("ldmatrix.sync.aligned.m8n8.x4.shared.b16 {%0,%1,%2,%3}, [%4];" \
        : "=r"((r)[0]), "=r"((r)[1]), "=r"((r)[2]), "=r"((r)[3]) : "r"(addr))

#define MMA16816(c, a, b0, b1) \
    asm volatile("mma.sync.aligned.m16n8k16.row.col.f32.bf16.bf16.f32 " \
        "{%0,%1,%2,%3}, {%4,%5,%6,%7}, {%8,%9}, {%0,%1,%2,%3};" \
        : "+f"((c)[0]), "+f"((c)[1]), "+f"((c)[2]), "+f"((c)[3]) \
        : "r"((a)[0]), "r"((a)[1]), "r"((a)[2]), "r"((a)[3]), "r"(b0), "r"(b1))

__device__ __forceinline__ void cp16(uint32_t dst, const void* src) {
    asm volatile("cp.async.cg.shared.global [%0], [%1], 16;" :: "r"(dst), "l"(src));
}
#define CP_COMMIT() asm volatile("cp.async.commit_group;" ::: "memory")

__device__ __forceinline__ void split2(float a, float b, uint32_t& hi, uint32_t& lo) {
    __nv_bfloat162 h = __floats2bfloat162_rn(a, b);
    __nv_bfloat162 l = __floats2bfloat162_rn(a - __bfloat162float(h.x),
                                             b - __bfloat162float(h.y));
    hi = *reinterpret_cast<uint32_t*>(&h);
    lo = *reinterpret_cast<uint32_t*>(&l);
}

// prep: split weights to bf16 hi/lo; gather p_bias; reset ready counters.
__global__ __launch_bounds__(256) void prep_kernel(
    const float* __restrict__ Wq, const float* __restrict__ Wk,
    const float* __restrict__ Wv, const float* __restrict__ P)
{
    int i = blockIdx.x * blockDim.x + threadIdx.x;
    if (i < 128) g_ready[i] = 0;
    if (i < 4096) {
        g_pbias[i] = P[(size_t)(i >> 6) * 128 * T_DIM + (size_t)(i & 63) * 128];
    }
    if (i >= 384 * 1024) return;
    int r = i >> 10;
    const float* W = (r < 128) ? Wq : (r < 256) ? Wk : Wv;
    float v = W[(size_t)(r & 127) * 1024 + (i & 1023)];
    __nv_bfloat16 h = __float2bfloat16(v);
    g_whi[i] = h;
    g_wlo[i] = __float2bfloat16(v - __bfloat162float(h));
}

// ---- fused GEMM+attention kernel ----
// bids 0..383:  GEMM slab = bid%3, m-block = bid/3
// bids 384..639: attention group g = bid-384, waits g_ready[g>>1] == 3
#define STG   38912
#define BH_OFF 18432

__global__ __launch_bounds__(256, 2) void fused_kernel(
    const float* __restrict__ x, float* __restrict__ out)
{
    extern __shared__ char dsm[];
    const int bid = blockIdx.x;
    const int tid = threadIdx.x;

    if (bid < 384) {
        // ================= GEMM part =================
        const uint32_t smem_base = smem_u32(dsm);
        const int warp = tid >> 5, lane = tid & 31;
        const int nbase = (bid % 3) * 128;
        const int m0 = (bid / 3) * 128;

        const float* axp[4];
        const int arow_sub = tid >> 3;
        #pragma unroll
        for (int q = 0; q < 4; q++) {
            int r = m0 + arow_sub + q * 32;
            int b = r >> 12, j = (r >> 6) & 63, l = r & 63;
            axp[q] = x + ((size_t)b * T_DIM + (size_t)l * 128 + j) * E_DIM + (tid & 7) * 4;
        }
        const int brow_sub = tid >> 2;
        const __nv_bfloat16 *bhp[2], *blp[2];
        #pragma unroll
        for (int q = 0; q < 2; q++) {
            size_t off = (size_t)(nbase + brow_sub + q * 64) * 1024 + (tid & 3) * 8;
            bhp[q] = g_whi + off;
            blp[q] = g_wlo + off;
        }
        const uint32_t a_dst0 = arow_sub * 144 + (tid & 7) * 16;
        const uint32_t b_dst0 = brow_sub * 80 + (tid & 3) * 16;

        auto issue_stage = [&](int slot, int k0) {
            uint32_t sb = smem_base + slot * STG;
            #pragma unroll
            for (int q = 0; q < 4; q++)
                cp16(sb + a_dst0 + q * 4608, axp[q] + k0);
            #pragma unroll
            for (int q = 0; q < 2; q++) {
                cp16(sb + BH_OFF + b_dst0 + q * 5120, bhp[q] + k0);
                cp16(sb + BH_OFF + 10240 + b_dst0 + q * 5120, blp[q] + k0);
            }
        };

        const int m_w = (warp >> 1) * 32;
        const int n_w = (warp & 1) * 64;

        float acc[2][8][4];
        #pragma unroll
        for (int i = 0; i < 2; i++)
            #pragma unroll
            for (int j = 0; j < 8; j++)
                #pragma unroll
                for (int k = 0; k < 4; k++) acc[i][j][k] = 0.f;

        issue_stage(0, 0);  CP_COMMIT();
        issue_stage(1, 32); CP_COMMIT();

        for (int c = 0; c < 32; c++) {
            asm volatile("cp.async.wait_group 1;" ::: "memory");
            __syncthreads();

            const int slot = c & 1;
            const float* Asm = reinterpret_cast<const float*>(dsm + slot * STG);
            const uint32_t bbase = smem_base + slot * STG + BH_OFF;

            #pragma unroll
            for (int kst = 0; kst < 2; kst++) {
                // ---- build A fragments (hi/lo) from fp32 smem ----
                uint32_t ah[2][4], al[2][4];
                #pragma unroll
                for (int mt = 0; mt < 2; mt++) {
                    const float* ap = Asm + (m_w + mt * 16 + (lane >> 2)) * 36
                                    + kst * 16 + (lane & 3) * 2;
                    float2 v00 = *reinterpret_cast<const float2*>(ap);
                    float2 v10 = *reinterpret_cast<const float2*>(ap + 8 * 36);
                    float2 v01 = *reinterpret_cast<const float2*>(ap + 8);
                    float2 v11 = *reinterpret_cast<const float2*>(ap + 8 * 36 + 8);
                    split2(v00.x, v00.y, ah[mt][0], al[mt][0]);
                    split2(v10.x, v10.y, ah[mt][1], al[mt][1]);
                    split2(v01.x, v01.y, ah[mt][2], al[mt][2]);
                    split2(v11.x, v11.y, ah[mt][3], al[mt][3]);
                }
                // ---- load B-hi for BOTH nh halves (16 regs) ----
                uint32_t bb[2][2][4];
                uint32_t rbs[2][2];
                #pragma unroll
                for (int nh = 0; nh < 2; nh++)
                    #pragma unroll
                    for (int q = 0; q < 2; q++) {
                        rbs[nh][q] = bbase + (n_w + nh * 32 + q * 16 + (lane & 15)) * 80
                                   + kst * 32 + (lane >> 4) * 16;
                        LDSM4(bb[nh][q], rbs[nh][q]);
                    }
                // ---- hh: 16 independent MMAs (distance 16) ----
                #pragma unroll
                for (int mt = 0; mt < 2; mt++)
                    #pragma unroll
                    for (int nh = 0; nh < 2; nh++)
                        #pragma unroll
                        for (int q = 0; q < 2; q++)
                            #pragma unroll
                            for (int s = 0; s < 2; s++)
                                MMA16816(acc[mt][nh * 4 + q * 2 + s], ah[mt],
                                         bb[nh][q][s], bb[nh][q][s + 2]);
                // ---- lh: 16 independent MMAs ----
                #pragma unroll
                for (int mt = 0; mt < 2; mt++)
                    #pragma unroll
                    for (int nh = 0; nh < 2; nh++)
                        #pragma unroll
                        for (int q = 0; q < 2; q++)
                            #pragma unroll
                            for (int s = 0; s < 2; s++)
                                MMA16816(acc[mt][nh * 4 + q * 2 + s], al[mt],
                                         bb[nh][q][s], bb[nh][q][s + 2]);
                // ---- overwrite b-regs with B-lo, then hl: 16 MMAs ----
                #pragma unroll
                for (int nh = 0; nh < 2; nh++)
                    #pragma unroll
                    for (int q = 0; q < 2; q++)
                        LDSM4(bb[nh][q], rbs[nh][q] + 10240);
                #pragma unroll
                for (int mt = 0; mt < 2; mt++)
                    #pragma unroll
                    for (int nh = 0; nh < 2; nh++)
                        #pragma unroll
                        for (int q = 0; q < 2; q++)
                            #pragma unroll
                            for (int s = 0; s < 2; s++)
                                MMA16816(acc[mt][nh * 4 + q * 2 + s], ah[mt],
                                         bb[nh][q][s], bb[nh][q][s + 2]);
            }

            __syncthreads();
            if (c < 30) issue_stage(slot, (c + 2) * 32);
            CP_COMMIT();
        }

        #pragma unroll
        for (int mt = 0; mt < 2; mt++) {
            #pragma unroll
            for (int nt = 0; nt < 8; nt++) {
                int row0 = m0 + m_w + mt * 16 + (lane >> 2);
                int col = nbase + n_w + nt * 8 + (lane & 3) * 2;
                float* p0 = &g_qkv[(size_t)row0 * 384 + col];
                float* p1 = &g_qkv[(size_t)(row0 + 8) * 384 + col];
                *reinterpret_cast<float2*>(p0) = make_float2(acc[mt][nt][0], acc[mt][nt][1]);
                *reinterpret_cast<float2*>(p1) = make_float2(acc[mt][nt][2], acc[mt][nt][3]);
            }
        }
        __threadfence();
        __syncthreads();
        if (tid == 0) atomicAdd(&g_ready[bid / 3], 1);

    } else {
        // ================= attention part =================
        float* sm = reinterpret_cast<float*>(dsm);
        float* Kt  = sm;                  // [128][68] transposed: Kt[p][k]
        float* Vs  = Kt + 128 * 68;       // [64][128]
        float* QtS = Vs + 64 * 128;       // [128][68] Qt[p][o], overlaid by S[64][68]
        const int g = bid - 384;
        const int mb = g >> 1;
        const int bbk = g >> 6, jseg = g & 63;
        const float* base = g_qkv + (size_t)g * 64 * 384;

        if (tid == 0) {
            int v;
            do {
                asm volatile("ld.acquire.gpu.s32 %0, [%1];" : "=r"(v) : "l"(g_ready + mb));
                if (v < 3) __nanosleep(128);
            } while (v < 3);
        }
        __syncthreads();

        for (int idx = tid; idx < 64 * 32; idx += 256) {
            int row = idx >> 5;
            int c4 = (idx & 31) * 4;
            const float* rp = base + (size_t)row * 384;
            float4 qv = *reinterpret_cast<const float4*>(rp + c4);
            float4 kv = *reinterpret_cast<const float4*>(rp + 128 + c4);
            float4 vv = *reinterpret_cast<const float4*>(rp + 256 + c4);
            *reinterpret_cast<float4*>(Vs + row * 128 + c4) = vv;
            Kt[(c4 + 0) * 68 + row] = kv.x;
            Kt[(c4 + 1) * 68 + row] = kv.y;
            Kt[(c4 + 2) * 68 + row] = kv.z;
            Kt[(c4 + 3) * 68 + row] = kv.w;
            QtS[(c4 + 0) * 68 + row] = qv.x;
            QtS[(c4 + 1) * 68 + row] = qv.y;
            QtS[(c4 + 2) * 68 + row] = qv.z;
            QtS[(c4 + 3) * 68 + row] = qv.w;
        }
        __syncthreads();

        const int tk = tid >> 4, to = tid & 15;
        float4 sval[4];
        {
            float sacc[4][4];
            #pragma unroll
            for (int i = 0; i < 4; i++)
                #pragma unroll
                for (int j = 0; j < 4; j++) sacc[i][j] = 0.f;
            for (int p = 0; p < 128; p++) {
                float4 rk = *reinterpret_cast<const float4*>(Kt + p * 68 + tk * 4);
                float4 rq = *reinterpret_cast<const float4*>(QtS + p * 68 + to * 4);
                float ka[4] = {rk.x, rk.y, rk.z, rk.w};
                float qa[4] = {rq.x, rq.y, rq.z, rq.w};
                #pragma unroll
                for (int i = 0; i < 4; i++)
                    #pragma unroll
                    for (int j = 0; j < 4; j++)
                        sacc[i][j] = fmaf(ka[i], qa[j], sacc[i][j]);
            }
            const float nf = 0.08838834764831845f;  // 1/sqrt(128)
            #pragma unroll
            for (int i = 0; i < 4; i++) {
                int k = tk * 4 + i;
                float e[4];
                #pragma unroll
                for (int j = 0; j < 4; j++) {
                    int o = to * 4 + j;
                    float v = (k >= o) ? sacc[i][j] : -10000.0f;
                    v += g_pbias[k * 64 + o];
                    e[j] = v * nf;
                }
                sval[i] = make_float4(e[0], e[1], e[2], e[3]);
            }
        }
        __syncthreads();
        #pragma unroll
        for (int i = 0; i < 4; i++)
            *reinterpret_cast<float4*>(QtS + (tk * 4 + i) * 68 + to * 4) = sval[i];
        __syncthreads();

        {
            const int o = tid >> 2, seg = tid & 3;
            float e[16];
            float mx = -3.402823466e38f;
            #pragma unroll
            for (int i = 0; i < 16; i++) {
                e[i] = QtS[(seg * 16 + i) * 68 + o];
                mx = fmaxf(mx, e[i]);
            }
            mx = fmaxf(mx, __shfl_xor_sync(0xffffffffu, mx, 1));
            mx = fmaxf(mx, __shfl_xor_sync(0xffffffffu, mx, 2));
            float ssum = 0.f;
            #pragma unroll
            for (int i = 0; i < 16; i++) { e[i] = __expf(e[i] - mx); ssum += e[i]; }
            ssum += __shfl_xor_sync(0xffffffffu, ssum, 1);
            ssum += __shfl_xor_sync(0xffffffffu, ssum, 2);
            float inv = 1.0f / ssum;
            #pragma unroll
            for (int i = 0; i < 16; i++)
                QtS[(seg * 16 + i) * 68 + o] = e[i] * inv;
        }
        __syncthreads();

        {
            const int td = tid >> 4, tmm = tid & 15;
            float acc[4][8];
            #pragma unroll
            for (int i = 0; i < 4; i++)
                #pragma unroll
                for (int j = 0; j < 8; j++) acc[i][j] = 0.f;
            for (int k = 0; k < 64; k++) {
                float4 rs4 = *reinterpret_cast<const float4*>(QtS + k * 68 + td * 4);
                float rs[4] = {rs4.x, rs4.y, rs4.z, rs4.w};
                float4 v0 = *reinterpret_cast<const float4*>(Vs + k * 128 + tmm * 8);
                float4 v1 = *reinterpret_cast<const float4*>(Vs + k * 128 + tmm * 8 + 4);
                float rv[8] = {v0.x, v0.y, v0.z, v0.w, v1.x, v1.y, v1.z, v1.w};
                #pragma unroll
                for (int i = 0; i < 4; i++)
                    #pragma unroll
                    for (int j = 0; j < 8; j++)
                        acc[i][j] = fmaf(rs[i], rv[j], acc[i][j]);
            }
            const float4 z = make_float4(0.f, 0.f, 0.f, 0.f);
            #pragma unroll
            for (int i = 0; i < 4; i++) {
                int d = td * 4 + i;
                size_t orow = (size_t)bbk * T_DIM + 2 * ((size_t)jseg * 64 + d);
                float* op = out + orow * 128 + tmm * 8;
                *reinterpret_cast<float4*>(op)     = make_float4(acc[i][0], acc[i][1], acc[i][2], acc[i][3]);
                *reinterpret_cast<float4*>(op + 4) = make_float4(acc[i][4], acc[i][5], acc[i][6], acc[i][7]);
                float* oz = op + 128;   // odd row (poisoned) -> zero
                *reinterpret_cast<float4*>(oz)     = z;
                *reinterpret_cast<float4*>(oz + 4) = z;
            }
        }
    }
}

extern "C" void kernel_launch(void* const* d_in, const int* in_sizes, int n_in,
                              void* d_out, int out_size) {
    const float* x  = (const float*)d_in[0];   // x_in  [4, 8192, 1024]
    const float* P  = (const float*)d_in[1];   // P     [8192, 8192]
    const float* Wk = (const float*)d_in[2];   // Wk    [128, 1024]
    const float* Wq = (const float*)d_in[3];   // Wq    [128, 1024]
    const float* Wv = (const float*)d_in[4];   // Wv    [128, 1024]
    float* out = (float*)d_out;                // [4, 8192, 128] fp32

    prep_kernel<<<1536, 256>>>(Wq, Wk, Wv, P);

    // attn smem need: (128*68 + 64*128 + 128*68)*4 = 102400 B (> GEMM's 77824)
    int fsm = 102400;
    cudaFuncSetAttribute(fused_kernel, cudaFuncAttributeMaxDynamicSharedMemorySize, fsm);
    fused_kernel<<<640, 256, fsm>>>(x, out);
}

// round 11
// speedup vs baseline: 1.3073x; 1.1411x over previous
#include <cuda_runtime.h>
#include <cuda_fp16.h>
#include <cstdint>

#define E_DIM 1024
#define T_DIM 8192

// Scratch: QKV for the 16384 dilated tokens, layout [row][384] = Q|K|V.
__device__ float g_qkv[16384 * 384];
// fp16 weight hi/lo planes, rows 0-127=Wq, 128-255=Wk, 256-383=Wv
__device__ __half g_whi[384 * 1024];
__device__ __half g_wlo[384 * 1024];
// Gathered positional bias p_bias[k][o]
__device__ float g_pbias[64 * 64];
// Per-m-block completion counters (3 slabs each)
__device__ int g_ready[128];

__device__ __forceinline__ uint32_t smem_u32(const void* p) {
    uint32_t a;
    asm("{ .reg .u64 t; cvta.to.shared.u64 t, %1; cvt.u32.u64 %0, t; }" : "=r"(a) : "l"(p));
    return a;
}

#define LDSM4(r, addr) \
    asm volatile("ldmatrix.sync.aligned.m8n8.x4.shared.b16 {%0,%1,%2,%3}, [%4];" \
        : "=r"((r)[0]), "=r"((r)[1]), "=r"((r)[2]), "=r"((r)[3]) : "r"(addr))

#define MMAF16(c, a, b0, b1) \
    asm volatile("mma.sync.aligned.m16n8k16.row.col.f32.f16.f16.f32 " \
        "{%0,%1,%2,%3}, {%4,%5,%6,%7}, {%8,%9}, {%0,%1,%2,%3};" \
        : "+f"((c)[0]), "+f"((c)[1]), "+f"((c)[2]), "+f"((c)[3]) \
        : "r"((a)[0]), "r"((a)[1]), "r"((a)[2]), "r"((a)[3]), "r"(b0), "r"(b1))

__device__ __forceinline__ void cp16(uint32_t dst, const void* src) {
    asm volatile("cp.async.cg.shared.global [%0], [%1], 16;" :: "r"(dst), "l"(src));
}
#define CP_COMMIT() asm volatile("cp.async.commit_group;" ::: "memory")

__device__ __forceinline__ uint32_t packh2(float a, float b) {
    __half2 h = __floats2half2_rn(a, b);
    return *reinterpret_cast<uint32_t*>(&h);
}

// prep: split weights to fp16 hi/lo; gather p_bias; reset ready counters.
__global__ __launch_bounds__(256) void prep_kernel(
    const float* __restrict__ Wq, const float* __restrict__ Wk,
    const float* __restrict__ Wv, const float* __restrict__ P)
{
    int i = blockIdx.x * blockDim.x + threadIdx.x;
    if (i < 128) g_ready[i] = 0;
    if (i < 4096) {
        g_pbias[i] = P[(size_t)(i >> 6) * 128 * T_DIM + (size_t)(i & 63) * 128];
    }
    if (i >= 384 * 1024) return;
    int r = i >> 10;
    const float* W = (r < 128) ? Wq : (r < 256) ? Wk : Wv;
    float v = W[(size_t)(r & 127) * 1024 + (i & 1023)];
    __half h = __float2half_rn(v);
    g_whi[i] = h;
    g_wlo[i] = __float2half_rn(v - __half2float(h));
}

// ---- fused GEMM+attention kernel ----
// bids 0..383:  GEMM slab = bid%3, m-block = bid/3
// bids 384..639: attention group g = bid-384, waits g_ready[g>>1] == 3
#define STG   38912
#define BH_OFF 18432

__global__ __launch_bounds__(256, 2) void fused_kernel(
    const float* __restrict__ x, float* __restrict__ out)
{
    extern __shared__ char dsm[];
    const int bid = blockIdx.x;
    const int tid = threadIdx.x;

    if (bid < 384) {
        // ================= GEMM part =================
        const uint32_t smem_base = smem_u32(dsm);
        const int warp = tid >> 5, lane = tid & 31;
        const int nbase = (bid % 3) * 128;
        const int m0 = (bid / 3) * 128;

        const float* axp[4];
        const int arow_sub = tid >> 3;
        #pragma unroll
        for (int q = 0; q < 4; q++) {
            int r = m0 + arow_sub + q * 32;
            int b = r >> 12, j = (r >> 6) & 63, l = r & 63;
            axp[q] = x + ((size_t)b * T_DIM + (size_t)l * 128 + j) * E_DIM + (tid & 7) * 4;
        }
        const int brow_sub = tid >> 2;
        const __half *bhp[2], *blp[2];
        #pragma unroll
        for (int q = 0; q < 2; q++) {
            size_t off = (size_t)(nbase + brow_sub + q * 64) * 1024 + (tid & 3) * 8;
            bhp[q] = g_whi + off;
            blp[q] = g_wlo + off;
        }
        const uint32_t a_dst0 = arow_sub * 144 + (tid & 7) * 16;
        const uint32_t b_dst0 = brow_sub * 80 + (tid & 3) * 16;

        auto issue_stage = [&](int slot, int k0) {
            uint32_t sb = smem_base + slot * STG;
            #pragma unroll
            for (int q = 0; q < 4; q++)
                cp16(sb + a_dst0 + q * 4608, axp[q] + k0);
            #pragma unroll
            for (int q = 0; q < 2; q++) {
                cp16(sb + BH_OFF + b_dst0 + q * 5120, bhp[q] + k0);
                cp16(sb + BH_OFF + 10240 + b_dst0 + q * 5120, blp[q] + k0);
            }
        };

        const int m_w = (warp >> 1) * 32;
        const int n_w = (warp & 1) * 64;

        float acc[2][8][4];
        #pragma unroll
        for (int i = 0; i < 2; i++)
            #pragma unroll
            for (int j = 0; j < 8; j++)
                #pragma unroll
                for (int k = 0; k < 4; k++) acc[i][j][k] = 0.f;

        issue_stage(0, 0);  CP_COMMIT();
        issue_stage(1, 32); CP_COMMIT();

        for (int c = 0; c < 32; c++) {
            asm volatile("cp.async.wait_group 1;" ::: "memory");
            __syncthreads();

            const int slot = c & 1;
            const float* Asm = reinterpret_cast<const float*>(dsm + slot * STG);
            const uint32_t bbase = smem_base + slot * STG + BH_OFF;

            #pragma unroll
            for (int kst = 0; kst < 2; kst++) {
                // ---- build A fragments (single fp16) from fp32 smem ----
                uint32_t ah[2][4];
                #pragma unroll
                for (int mt = 0; mt < 2; mt++) {
                    const float* ap = Asm + (m_w + mt * 16 + (lane >> 2)) * 36
                                    + kst * 16 + (lane & 3) * 2;
                    float2 v00 = *reinterpret_cast<const float2*>(ap);
                    float2 v10 = *reinterpret_cast<const float2*>(ap + 8 * 36);
                    float2 v01 = *reinterpret_cast<const float2*>(ap + 8);
                    float2 v11 = *reinterpret_cast<const float2*>(ap + 8 * 36 + 8);
                    ah[mt][0] = packh2(v00.x, v00.y);
                    ah[mt][1] = packh2(v10.x, v10.y);
                    ah[mt][2] = packh2(v01.x, v01.y);
                    ah[mt][3] = packh2(v11.x, v11.y);
                }
                // ---- load B-hi and B-lo for both nh halves ----
                uint32_t bh[2][2][4], bl[2][2][4];
                #pragma unroll
                for (int nh = 0; nh < 2; nh++)
                    #pragma unroll
                    for (int q = 0; q < 2; q++) {
                        uint32_t rb = bbase + (n_w + nh * 32 + q * 16 + (lane & 15)) * 80
                                    + kst * 32 + (lane >> 4) * 16;
                        LDSM4(bh[nh][q], rb);
                        LDSM4(bl[nh][q], rb + 10240);
                    }
                // ---- a*bh: 16 independent MMAs (distance 16) ----
                #pragma unroll
                for (int mt = 0; mt < 2; mt++)
                    #pragma unroll
                    for (int nh = 0; nh < 2; nh++)
                        #pragma unroll
                        for (int q = 0; q < 2; q++)
                            #pragma unroll
                            for (int s = 0; s < 2; s++)
                                MMAF16(acc[mt][nh * 4 + q * 2 + s], ah[mt],
                                       bh[nh][q][s], bh[nh][q][s + 2]);
                // ---- a*bl: 16 independent MMAs ----
                #pragma unroll
                for (int mt = 0; mt < 2; mt++)
                    #pragma unroll
                    for (int nh = 0; nh < 2; nh++)
                        #pragma unroll
                        for (int q = 0; q < 2; q++)
                            #pragma unroll
                            for (int s = 0; s < 2; s++)
                                MMAF16(acc[mt][nh * 4 + q * 2 + s], ah[mt],
                                       bl[nh][q][s], bl[nh][q][s + 2]);
            }

            __syncthreads();
            if (c < 30) issue_stage(slot, (c + 2) * 32);
            CP_COMMIT();
        }

        #pragma unroll
        for (int mt = 0; mt < 2; mt++) {
            #pragma unroll
            for (int nt = 0; nt < 8; nt++) {
                int row0 = m0 + m_w + mt * 16 + (lane >> 2);
                int col = nbase + n_w + nt * 8 + (lane & 3) * 2;
                float* p0 = &g_qkv[(size_t)row0 * 384 + col];
                float* p1 = &g_qkv[(size_t)(row0 + 8) * 384 + col];
                *reinterpret_cast<float2*>(p0) = make_float2(acc[mt][nt][0], acc[mt][nt][1]);
                *reinterpret_cast<float2*>(p1) = make_float2(acc[mt][nt][2], acc[mt][nt][3]);
            }
        }
        __threadfence();
        __syncthreads();
        if (tid == 0) atomicAdd(&g_ready[bid / 3], 1);

    } else {
        // ================= attention part =================
        float* sm = reinterpret_cast<float*>(dsm);
        float* Kt  = sm;                  // [128][68] transposed: Kt[p][k]
        float* Vs  = Kt + 128 * 68;       // [64][128]
        float* QtS = Vs + 64 * 128;       // [128][68] Qt[p][o], overlaid by S[64][68]
        const int g = bid - 384;
        const int mb = g >> 1;
        const int bbk = g >> 6, jseg = g & 63;
        const float* base = g_qkv + (size_t)g * 64 * 384;

        if (tid == 0) {
            int v;
            do {
                asm volatile("ld.acquire.gpu.s32 %0, [%1];" : "=r"(v) : "l"(g_ready + mb));
                if (v < 3) __nanosleep(128);
            } while (v < 3);
        }
        __syncthreads();

        for (int idx = tid; idx < 64 * 32; idx += 256) {
            int row = idx >> 5;
            int c4 = (idx & 31) * 4;
            const float* rp = base + (size_t)row * 384;
            float4 qv = *reinterpret_cast<const float4*>(rp + c4);
            float4 kv = *reinterpret_cast<const float4*>(rp + 128 + c4);
            float4 vv = *reinterpret_cast<const float4*>(rp + 256 + c4);
            *reinterpret_cast<float4*>(Vs + row * 128 + c4) = vv;
            Kt[(c4 + 0) * 68 + row] = kv.x;
            Kt[(c4 + 1) * 68 + row] = kv.y;
            Kt[(c4 + 2) * 68 + row] = kv.z;
            Kt[(c4 + 3) * 68 + row] = kv.w;
            QtS[(c4 + 0) * 68 + row] = qv.x;
            QtS[(c4 + 1) * 68 + row] = qv.y;
            QtS[(c4 + 2) * 68 + row] = qv.z;
            QtS[(c4 + 3) * 68 + row] = qv.w;
        }
        __syncthreads();

        const int tk = tid >> 4, to = tid & 15;
        float4 sval[4];
        {
            float sacc[4][4];
            #pragma unroll
            for (int i = 0; i < 4; i++)
                #pragma unroll
                for (int j = 0; j < 4; j++) sacc[i][j] = 0.f;
            for (int p = 0; p < 128; p++) {
                float4 rk = *reinterpret_cast<const float4*>(Kt + p * 68 + tk * 4);
                float4 rq = *reinterpret_cast<const float4*>(QtS + p * 68 + to * 4);
                float ka[4] = {rk.x, rk.y, rk.z, rk.w};
                float qa[4] = {rq.x, rq.y, rq.z, rq.w};
                #pragma unroll
                for (int i = 0; i < 4; i++)
                    #pragma unroll
                    for (int j = 0; j < 4; j++)
                        sacc[i][j] = fmaf(ka[i], qa[j], sacc[i][j]);
            }
            const float nf = 0.08838834764831845f;  // 1/sqrt(128)
            #pragma unroll
            for (int i = 0; i < 4; i++) {
                int k = tk * 4 + i;
                float e[4];
                #pragma unroll
                for (int j = 0; j < 4; j++) {
                    int o = to * 4 + j;
                    float v = (k >= o) ? sacc[i][j] : -10000.0f;
                    v += g_pbias[k * 64 + o];
                    e[j] = v * nf;
                }
                sval[i] = make_float4(e[0], e[1], e[2], e[3]);
            }
        }
        __syncthreads();
        #pragma unroll
        for (int i = 0; i < 4; i++)
            *reinterpret_cast<float4*>(QtS + (tk * 4 + i) * 68 + to * 4) = sval[i];
        __syncthreads();

        {
            const int o = tid >> 2, seg = tid & 3;
            float e[16];
            float mx = -3.402823466e38f;
            #pragma unroll
            for (int i = 0; i < 16; i++) {
                e[i] = QtS[(seg * 16 + i) * 68 + o];
                mx = fmaxf(mx, e[i]);
            }
            mx = fmaxf(mx, __shfl_xor_sync(0xffffffffu, mx, 1));
            mx = fmaxf(mx, __shfl_xor_sync(0xffffffffu, mx, 2));
            float ssum = 0.f;
            #pragma unroll
            for (int i = 0; i < 16; i++) { e[i] = __expf(e[i] - mx); ssum += e[i]; }
            ssum += __shfl_xor_sync(0xffffffffu, ssum, 1);
            ssum += __shfl_xor_sync(0xffffffffu, ssum, 2);
            float inv = 1.0f / ssum;
            #pragma unroll
            for (int i = 0; i < 16; i++)
                QtS[(seg * 16 + i) * 68 + o] = e[i] * inv;
        }
        __syncthreads();

        {
            const int td = tid >> 4, tmm = tid & 15;
            float acc[4][8];
            #pragma unroll
            for (int i = 0; i < 4; i++)
                #pragma unroll
                for (int j = 0; j < 8; j++) acc[i][j] = 0.f;
            for (int k = 0; k < 64; k++) {
                float4 rs4 = *reinterpret_cast<const float4*>(QtS + k * 68 + td * 4);
                float rs[4] = {rs4.x, rs4.y, rs4.z, rs4.w};
                float4 v0 = *reinterpret_cast<const float4*>(Vs + k * 128 + tmm * 8);
                float4 v1 = *reinterpret_cast<const float4*>(Vs + k * 128 + tmm * 8 + 4);
                float rv[8] = {v0.x, v0.y, v0.z, v0.w, v1.x, v1.y, v1.z, v1.w};
                #pragma unroll
                for (int i = 0; i < 4; i++)
                    #pragma unroll
                    for (int j = 0; j < 8; j++)
                        acc[i][j] = fmaf(rs[i], rv[j], acc[i][j]);
            }
            const float4 z = make_float4(0.f, 0.f, 0.f, 0.f);
            #pragma unroll
            for (int i = 0; i < 4; i++) {
                int d = td * 4 + i;
                size_t orow = (size_t)bbk * T_DIM + 2 * ((size_t)jseg * 64 + d);
                float* op = out + orow * 128 + tmm * 8;
                *reinterpret_cast<float4*>(op)     = make_float4(acc[i][0], acc[i][1], acc[i][2], acc[i][3]);
                *reinterpret_cast<float4*>(op + 4) = make_float4(acc[i][4], acc[i][5], acc[i][6], acc[i][7]);
                float* oz = op + 128;   // odd row (poisoned) -> zero
                *reinterpret_cast<float4*>(oz)     = z;
                *reinterpret_cast<float4*>(oz + 4) = z;
            }
        }
    }
}

extern "C" void kernel_launch(void* const* d_in, const int* in_sizes, int n_in,
                              void* d_out, int out_size) {
    const float* x  = (const float*)d_in[0];   // x_in  [4, 8192, 1024]
    const float* P  = (const float*)d_in[1];   // P     [8192, 8192]
    const float* Wk = (const float*)d_in[2];   // Wk    [128, 1024]
    const float* Wq = (const float*)d_in[3];   // Wq    [128, 1024]
    const float* Wv = (const float*)d_in[4];   // Wv    [128, 1024]
    float* out = (float*)d_out;                // [4, 8192, 128] fp32

    prep_kernel<<<1536, 256>>>(Wq, Wk, Wv, P);

    // attn smem need: (128*68 + 64*128 + 128*68)*4 = 102400 B (> GEMM's 77824)
    int fsm = 102400;
    cudaFuncSetAttribute(fused_kernel, cudaFuncAttributeMaxDynamicSharedMemorySize, fsm);
    fused_kernel<<<640, 256, fsm>>>(x, out);
}

// round 12
// speedup vs baseline: 1.3993x; 1.0704x over previous
#include <cuda_runtime.h>
#include <cuda_fp16.h>
#include <cstdint>

#define E_DIM 1024
#define T_DIM 8192

// Scratch: QKV for the 16384 dilated tokens, layout [row][384] = Q|K|V.
__device__ float g_qkv[16384 * 384];
// fp16 weight hi/lo planes, rows 0-127=Wq, 128-255=Wk, 256-383=Wv
__device__ __half g_whi[384 * 1024];
__device__ __half g_wlo[384 * 1024];
// Gathered positional bias p_bias[k][o]
__device__ float g_pbias[64 * 64];
// Per-m-block completion counters (3 slabs each)
__device__ int g_ready[128];

__device__ __forceinline__ uint32_t smem_u32(const void* p) {
    uint32_t a;
    asm("{ .reg .u64 t; cvta.to.shared.u64 t, %1; cvt.u32.u64 %0, t; }" : "=r"(a) : "l"(p));
    return a;
}

#define LDSM4(r, addr) \
    asm volatile("ldmatrix.sync.aligned.m8n8.x4.shared.b16 {%0,%1,%2,%3}, [%4];" \
        : "=r"((r)[0]), "=r"((r)[1]), "=r"((r)[2]), "=r"((r)[3]) : "r"(addr))

#define MMAF16(c, a, b0, b1) \
    asm volatile("mma.sync.aligned.m16n8k16.row.col.f32.f16.f16.f32 " \
        "{%0,%1,%2,%3}, {%4,%5,%6,%7}, {%8,%9}, {%0,%1,%2,%3};" \
        : "+f"((c)[0]), "+f"((c)[1]), "+f"((c)[2]), "+f"((c)[3]) \
        : "r"((a)[0]), "r"((a)[1]), "r"((a)[2]), "r"((a)[3]), "r"(b0), "r"(b1))

__device__ __forceinline__ void cp16(uint32_t dst, const void* src) {
    asm volatile("cp.async.cg.shared.global [%0], [%1], 16;" :: "r"(dst), "l"(src));
}
#define CP_COMMIT() asm volatile("cp.async.commit_group;" ::: "memory")

__device__ __forceinline__ uint32_t packh2(float a, float b) {
    __half2 h = __floats2half2_rn(a, b);
    return *reinterpret_cast<uint32_t*>(&h);
}

// prep: split weights to fp16 hi/lo; gather p_bias; reset ready counters.
__global__ __launch_bounds__(256) void prep_kernel(
    const float* __restrict__ Wq, const float* __restrict__ Wk,
    const float* __restrict__ Wv, const float* __restrict__ P)
{
    int i = blockIdx.x * blockDim.x + threadIdx.x;
    if (i < 128) g_ready[i] = 0;
    if (i < 4096) {
        g_pbias[i] = P[(size_t)(i >> 6) * 128 * T_DIM + (size_t)(i & 63) * 128];
    }
    if (i >= 384 * 1024) return;
    int r = i >> 10;
    const float* W = (r < 128) ? Wq : (r < 256) ? Wk : Wv;
    float v = W[(size_t)(r & 127) * 1024 + (i & 1023)];
    __half h = __float2half_rn(v);
    g_whi[i] = h;
    g_wlo[i] = __float2half_rn(v - __half2float(h));
}

// ---- fused GEMM+attention kernel ----
// bids 0..383:  GEMM slab = bid%3, m-block = bid/3
// bids 384..639: attention group g = bid-384, waits g_ready[g>>1] == 3
// GEMM stage (30720B): A fp16 [128x80]@0, Bhi@10240, Blo@20480; 3 stages = 92160.
#define STG 30720

__global__ __launch_bounds__(256, 2) void fused_kernel(
    const float* __restrict__ x, float* __restrict__ out)
{
    extern __shared__ char dsm[];
    const int bid = blockIdx.x;
    const int tid = threadIdx.x;

    if (bid < 384) {
        // ================= GEMM part =================
        const uint32_t smem_base = smem_u32(dsm);
        const int warp = tid >> 5, lane = tid & 31;
        const int nbase = (bid % 3) * 128;
        const int m0 = (bid / 3) * 128;

        // A loader: 2 threads/row, 16 source floats (=32B fp16 out) each
        const int lrow = tid >> 1;
        const int seg = tid & 1;
        const float* arow;
        {
            int r = m0 + lrow;
            int b = r >> 12, j = (r >> 6) & 63, l = r & 63;
            arow = x + ((size_t)b * T_DIM + (size_t)l * 128 + j) * E_DIM + seg * 16;
        }
        const uint32_t a_dst0 = lrow * 80 + seg * 32;

        // B loader: 4 threads/row, 16B each, rows +0/+64
        const int brow_sub = tid >> 2;
        const __half *bhp[2], *blp[2];
        #pragma unroll
        for (int q = 0; q < 2; q++) {
            size_t off = (size_t)(nbase + brow_sub + q * 64) * 1024 + (tid & 3) * 8;
            bhp[q] = g_whi + off;
            blp[q] = g_wlo + off;
        }
        const uint32_t b_dst0 = brow_sub * 80 + (tid & 3) * 16;

        float aregs[16];
        auto ldga = [&](int chunk) {
            const float* p = arow + chunk * 32;
            #pragma unroll
            for (int q = 0; q < 4; q++)
                *reinterpret_cast<float4*>(aregs + q * 4) =
                    *reinterpret_cast<const float4*>(p + q * 4);
        };
        auto stsa = [&](int slot) {
            uint32_t h2[8];
            #pragma unroll
            for (int q = 0; q < 8; q++)
                h2[q] = packh2(aregs[2 * q], aregs[2 * q + 1]);
            char* d = dsm + slot * STG + a_dst0;
            *reinterpret_cast<uint4*>(d)      = make_uint4(h2[0], h2[1], h2[2], h2[3]);
            *reinterpret_cast<uint4*>(d + 16) = make_uint4(h2[4], h2[5], h2[6], h2[7]);
        };
        auto cpb = [&](int slot, int chunk) {
            uint32_t sb = smem_base + slot * STG;
            int k0 = chunk * 32;
            #pragma unroll
            for (int q = 0; q < 2; q++) {
                cp16(sb + 10240 + b_dst0 + q * 5120, bhp[q] + k0);
                cp16(sb + 20480 + b_dst0 + q * 5120, blp[q] + k0);
            }
        };

        const int m_w = (warp >> 1) * 32;
        const int n_w = (warp & 1) * 64;

        float acc[2][8][4];
        #pragma unroll
        for (int i = 0; i < 2; i++)
            #pragma unroll
            for (int j = 0; j < 8; j++)
                #pragma unroll
                for (int k = 0; k < 4; k++) acc[i][j][k] = 0.f;

        // prologue: chunks 0,1 staged; chunk 2 prefetched in regs
        ldga(0); stsa(0); cpb(0, 0); CP_COMMIT();
        ldga(1); stsa(1); cpb(1, 1); CP_COMMIT();
        ldga(2);

        for (int c = 0; c < 32; c++) {
            asm volatile("cp.async.wait_group 1;" ::: "memory");
            __syncthreads();

            const int slot = c % 3;
            const uint32_t stA = smem_base + slot * STG;
            const uint32_t stB = stA + 10240;

            #pragma unroll
            for (int kst = 0; kst < 2; kst++) {
                uint32_t ah[2][4];
                #pragma unroll
                for (int mt = 0; mt < 2; mt++) {
                    uint32_t ra = stA + (m_w + mt * 16 + (lane & 15)) * 80
                                + kst * 32 + (lane >> 4) * 16;
                    LDSM4(ah[mt], ra);
                }
                uint32_t bb[2][2][4];
                uint32_t rbs[2][2];
                #pragma unroll
                for (int nh = 0; nh < 2; nh++)
                    #pragma unroll
                    for (int q = 0; q < 2; q++) {
                        rbs[nh][q] = stB + (n_w + nh * 32 + q * 16 + (lane & 15)) * 80
                                   + kst * 32 + (lane >> 4) * 16;
                        LDSM4(bb[nh][q], rbs[nh][q]);
                    }
                // a*bh: 16 independent MMAs
                #pragma unroll
                for (int mt = 0; mt < 2; mt++)
                    #pragma unroll
                    for (int nh = 0; nh < 2; nh++)
                        #pragma unroll
                        for (int q = 0; q < 2; q++)
                            #pragma unroll
                            for (int s = 0; s < 2; s++)
                                MMAF16(acc[mt][nh * 4 + q * 2 + s], ah[mt],
                                       bb[nh][q][s], bb[nh][q][s + 2]);
                // reload b-regs with B-lo, a*bl: 16 MMAs
                #pragma unroll
                for (int nh = 0; nh < 2; nh++)
                    #pragma unroll
                    for (int q = 0; q < 2; q++)
                        LDSM4(bb[nh][q], rbs[nh][q] + 10240);
                #pragma unroll
                for (int mt = 0; mt < 2; mt++)
                    #pragma unroll
                    for (int nh = 0; nh < 2; nh++)
                        #pragma unroll
                        for (int q = 0; q < 2; q++)
                            #pragma unroll
                            for (int s = 0; s < 2; s++)
                                MMAF16(acc[mt][nh * 4 + q * 2 + s], ah[mt],
                                       bb[nh][q][s], bb[nh][q][s + 2]);
            }

            // stage chunk c+2 into the slot retired at iter c-1 (barrier-protected)
            if (c < 30) {
                int ns = (c + 2) % 3;
                stsa(ns);
                cpb(ns, c + 2);
            }
            CP_COMMIT();
            if (c < 29) ldga(c + 3);
        }

        #pragma unroll
        for (int mt = 0; mt < 2; mt++) {
            #pragma unroll
            for (int nt = 0; nt < 8; nt++) {
                int row0 = m0 + m_w + mt * 16 + (lane >> 2);
                int col = nbase + n_w + nt * 8 + (lane & 3) * 2;
                float* p0 = &g_qkv[(size_t)row0 * 384 + col];
                float* p1 = &g_qkv[(size_t)(row0 + 8) * 384 + col];
                *reinterpret_cast<float2*>(p0) = make_float2(acc[mt][nt][0], acc[mt][nt][1]);
                *reinterpret_cast<float2*>(p1) = make_float2(acc[mt][nt][2], acc[mt][nt][3]);
            }
        }
        __threadfence();
        __syncthreads();
        if (tid == 0) atomicAdd(&g_ready[bid / 3], 1);

    } else {
        // ================= attention part =================
        float* sm = reinterpret_cast<float*>(dsm);
        float* Kt  = sm;                  // [128][68] transposed: Kt[p][k]
        float* Vs  = Kt + 128 * 68;       // [64][128]
        float* QtS = Vs + 64 * 128;       // [128][68] Qt[p][o], overlaid by S[64][68]
        const int g = bid - 384;
        const int mb = g >> 1;
        const int bbk = g >> 6, jseg = g & 63;
        const float* base = g_qkv + (size_t)g * 64 * 384;

        if (tid == 0) {
            int v;
            do {
                asm volatile("ld.acquire.gpu.s32 %0, [%1];" : "=r"(v) : "l"(g_ready + mb));
                if (v < 3) __nanosleep(128);
            } while (v < 3);
        }
        __syncthreads();

        for (int idx = tid; idx < 64 * 32; idx += 256) {
            int row = idx >> 5;
            int c4 = (idx & 31) * 4;
            const float* rp = base + (size_t)row * 384;
            float4 qv = *reinterpret_cast<const float4*>(rp + c4);
            float4 kv = *reinterpret_cast<const float4*>(rp + 128 + c4);
            float4 vv = *reinterpret_cast<const float4*>(rp + 256 + c4);
            *reinterpret_cast<float4*>(Vs + row * 128 + c4) = vv;
            Kt[(c4 + 0) * 68 + row] = kv.x;
            Kt[(c4 + 1) * 68 + row] = kv.y;
            Kt[(c4 + 2) * 68 + row] = kv.z;
            Kt[(c4 + 3) * 68 + row] = kv.w;
            QtS[(c4 + 0) * 68 + row] = qv.x;
            QtS[(c4 + 1) * 68 + row] = qv.y;
            QtS[(c4 + 2) * 68 + row] = qv.z;
            QtS[(c4 + 3) * 68 + row] = qv.w;
        }
        __syncthreads();

        const int tk = tid >> 4, to = tid & 15;
        float4 sval[4];
        {
            float sacc[4][4];
            #pragma unroll
            for (int i = 0; i < 4; i++)
                #pragma unroll
                for (int j = 0; j < 4; j++) sacc[i][j] = 0.f;
            for (int p = 0; p < 128; p++) {
                float4 rk = *reinterpret_cast<const float4*>(Kt + p * 68 + tk * 4);
                float4 rq = *reinterpret_cast<const float4*>(QtS + p * 68 + to * 4);
                float ka[4] = {rk.x, rk.y, rk.z, rk.w};
                float qa[4] = {rq.x, rq.y, rq.z, rq.w};
                #pragma unroll
                for (int i = 0; i < 4; i++)
                    #pragma unroll
                    for (int j = 0; j < 4; j++)
                        sacc[i][j] = fmaf(ka[i], qa[j], sacc[i][j]);
            }
            const float nf = 0.08838834764831845f;  // 1/sqrt(128)
            #pragma unroll
            for (int i = 0; i < 4; i++) {
                int k = tk * 4 + i;
                float e[4];
                #pragma unroll
                for (int j = 0; j < 4; j++) {
                    int o = to * 4 + j;
                    float v = (k >= o) ? sacc[i][j] : -10000.0f;
                    v += g_pbias[k * 64 + o];
                    e[j] = v * nf;
                }
                sval[i] = make_float4(e[0], e[1], e[2], e[3]);
            }
        }
        __syncthreads();
        #pragma unroll
        for (int i = 0; i < 4; i++)
            *reinterpret_cast<float4*>(QtS + (tk * 4 + i) * 68 + to * 4) = sval[i];
        __syncthreads();

        {
            const int o = tid >> 2, seg2 = tid & 3;
            float e[16];
            float mx = -3.402823466e38f;
            #pragma unroll
            for (int i = 0; i < 16; i++) {
                e[i] = QtS[(seg2 * 16 + i) * 68 + o];
                mx = fmaxf(mx, e[i]);
            }
            mx = fmaxf(mx, __shfl_xor_sync(0xffffffffu, mx, 1));
            mx = fmaxf(mx, __shfl_xor_sync(0xffffffffu, mx, 2));
            float ssum = 0.f;
            #pragma unroll
            for (int i = 0; i < 16; i++) { e[i] = __expf(e[i] - mx); ssum += e[i]; }
            ssum += __shfl_xor_sync(0xffffffffu, ssum, 1);
            ssum += __shfl_xor_sync(0xffffffffu, ssum, 2);
            float inv = 1.0f / ssum;
            #pragma unroll
            for (int i = 0; i < 16; i++)
                QtS[(seg2 * 16 + i) * 68 + o] = e[i] * inv;
        }
        __syncthreads();

        {
            const int td = tid >> 4, tmm = tid & 15;
            float acc[4][8];
            #pragma unroll
            for (int i = 0; i < 4; i++)
                #pragma unroll
                for (int j = 0; j < 8; j++) acc[i][j] = 0.f;
            for (int k = 0; k < 64; k++) {
                float4 rs4 = *reinterpret_cast<const float4*>(QtS + k * 68 + td * 4);
                float rs[4] = {rs4.x, rs4.y, rs4.z, rs4.w};
                float4 v0 = *reinterpret_cast<const float4*>(Vs + k * 128 + tmm * 8);
                float4 v1 = *reinterpret_cast<const float4*>(Vs + k * 128 + tmm * 8 + 4);
                float rv[8] = {v0.x, v0.y, v0.z, v0.w, v1.x, v1.y, v1.z, v1.w};
                #pragma unroll
                for (int i = 0; i < 4; i++)
                    #pragma unroll
                    for (int j = 0; j < 8; j++)
                        acc[i][j] = fmaf(rs[i], rv[j], acc[i][j]);
            }
            const float4 z = make_float4(0.f, 0.f, 0.f, 0.f);
            #pragma unroll
            for (int i = 0; i < 4; i++) {
                int d = td * 4 + i;
                size_t orow = (size_t)bbk * T_DIM + 2 * ((size_t)jseg * 64 + d);
                float* op = out + orow * 128 + tmm * 8;
                *reinterpret_cast<float4*>(op)     = make_float4(acc[i][0], acc[i][1], acc[i][2], acc[i][3]);
                *reinterpret_cast<float4*>(op + 4) = make_float4(acc[i][4], acc[i][5], acc[i][6], acc[i][7]);
                float* oz = op + 128;   // odd row (poisoned) -> zero
                *reinterpret_cast<float4*>(oz)     = z;
                *reinterpret_cast<float4*>(oz + 4) = z;
            }
        }
    }
}

extern "C" void kernel_launch(void* const* d_in, const int* in_sizes, int n_in,
                              void* d_out, int out_size) {
    const float* x  = (const float*)d_in[0];   // x_in  [4, 8192, 1024]
    const float* P  = (const float*)d_in[1];   // P     [8192, 8192]
    const float* Wk = (const float*)d_in[2];   // Wk    [128, 1024]
    const float* Wq = (const float*)d_in[3];   // Wq    [128, 1024]
    const float* Wv = (const float*)d_in[4];   // Wv    [128, 1024]
    float* out = (float*)d_out;                // [4, 8192, 128] fp32

    prep_kernel<<<1536, 256>>>(Wq, Wk, Wv, P);

    // attn smem need: (128*68 + 64*128 + 128*68)*4 = 102400 B (> GEMM's 92160)
    int fsm = 102400;
    cudaFuncSetAttribute(fused_kernel, cudaFuncAttributeMaxDynamicSharedMemorySize, fsm);
    fused_kernel<<<640, 256, fsm>>>(x, out);
}